// round 7
// baseline (speedup 1.0000x reference)
#include <cuda_runtime.h>
#include <cuda_bf16.h>
#include <math.h>
#include <stdint.h>

// ---------------------------------------------------------------------------
// TinyTransformer: L=4, T=1024, B=4, D=1024, H=16, DQK=DV=64, FF=4096
// Round 7 (= R6 resubmit after infra timeout): GEMM warp tile 64x64 (block
// 128x256) to halve smem BW per MAC; weights pre-rounded to tf32 so the
// cp.async B path is exact.
// ---------------------------------------------------------------------------

#define Lc   4
#define Tc   1024
#define Bc   4
#define Dc   1024
#define Hc   16
#define DQKc 64
#define DVc  64
#define FFc  4096
#define TBc  4096
#define HDc  1024
#define EPSc 1e-6f

// ---------------- scratch (static device memory; no allocations) -----------
#define OFF_H    0
#define OFF_F    16777216
#define OFF_Z    (OFF_F   + 4194304)
#define OFF_K    (OFF_Z   + 4194304)
#define OFF_Q    (OFF_K   + 4194304)
#define OFF_V    (OFF_Q   + 4194304)
#define OFF_ATT  (OFF_V   + 4194304)
#define OFF_X    (OFF_ATT + 4194304)
#define OFF_W1R  (OFF_X   + 4194304)     // 16777216 (L*D*FF)
#define OFF_W2R  (OFF_W1R + 16777216)    // 16777216 (L*FF*D)
#define OFF_WKR  (OFF_W2R + 16777216)    // 4194304
#define OFF_WQR  (OFF_WKR + 4194304)
#define OFF_WVR  (OFF_WQR + 4194304)
#define SCRATCH_FLOATS (OFF_WVR + 4194304)

__device__ float g_scratch[SCRATCH_FLOATS];

// ---------------- reductions ----------------------------------------------
__device__ __forceinline__ float warpReduceSum(float v) {
#pragma unroll
    for (int o = 16; o > 0; o >>= 1) v += __shfl_xor_sync(0xffffffffu, v, o);
    return v;
}
__device__ __forceinline__ float warpReduceMax(float v) {
#pragma unroll
    for (int o = 16; o > 0; o >>= 1) v = fmaxf(v, __shfl_xor_sync(0xffffffffu, v, o));
    return v;
}
__device__ float blockReduceSum(float v) {
    __shared__ float s[8];
    int lane = threadIdx.x & 31, w = threadIdx.x >> 5;
    v = warpReduceSum(v);
    if (lane == 0) s[w] = v;
    __syncthreads();
    float r = 0.f;
    if (threadIdx.x < 8) r = s[threadIdx.x];
    if (w == 0) r = warpReduceSum(r);
    if (threadIdx.x == 0) s[0] = r;
    __syncthreads();
    r = s[0];
    __syncthreads();
    return r;
}

// ---------------- tf32 / async helpers --------------------------------------
__device__ __forceinline__ uint32_t f2tf32(float x) {
    uint32_t r;
    asm("cvt.rna.tf32.f32 %0, %1;" : "=r"(r) : "f"(x));
    return r;
}
__device__ __forceinline__ void mma_tf32(float c[4], const uint32_t a[4],
                                         const uint32_t b[2]) {
    asm volatile(
        "mma.sync.aligned.m16n8k8.row.col.f32.tf32.tf32.f32 "
        "{%0,%1,%2,%3}, {%4,%5,%6,%7}, {%8,%9}, {%0,%1,%2,%3};"
        : "+f"(c[0]), "+f"(c[1]), "+f"(c[2]), "+f"(c[3])
        : "r"(a[0]), "r"(a[1]), "r"(a[2]), "r"(a[3]), "r"(b[0]), "r"(b[1]));
}
__device__ __forceinline__ uint32_t smem_u32(const void* p) {
    return (uint32_t)__cvta_generic_to_shared(p);
}
__device__ __forceinline__ void cpasync16(uint32_t dst, const void* src) {
    asm volatile("cp.async.ca.shared.global [%0], [%1], 16;" :: "r"(dst), "l"(src));
}
__device__ __forceinline__ void cpasync_commit() {
    asm volatile("cp.async.commit_group;");
}
__device__ __forceinline__ void cpasync_wait0() {
    asm volatile("cp.async.wait_group 0;");
}

// ---------------- weight pre-round: out = tf32_rna(in) ----------------------
__global__ __launch_bounds__(256)
void round_tf32_kernel(const float* __restrict__ in, float* __restrict__ outp) {
    int i = blockIdx.x * 256 + threadIdx.x;
    float4 v = ((const float4*)in)[i];
    uint4 o;
    o.x = f2tf32(v.x); o.y = f2tf32(v.y);
    o.z = f2tf32(v.z); o.w = f2tf32(v.w);
    ((uint4*)outp)[i] = o;
}

// ---------------- tf32 GEMM: C = relu?(A@B + bias) --------------------------
// A: MxK row-major fp32, B: KxN row-major fp32 (pre-rounded tf32), C: MxN fp32.
// Block 128x256x32, 256 threads = 8 warps (2x4), warp tile 64x64 (4mt x 8nt).
// A staged fragment-major tf32 (LDS.128 per fragment); B via cp.async,
// stride 264 -> fragment reads hit banks 8*tg+g (conflict-free).
// Double-buffered, one __syncthreads per chunk.
#define AF_STRIDE 132
#define AF_STAGE  (32 * AF_STRIDE)       // 4224 floats
#define BS_STRIDE 264
#define BS_STAGE  (32 * BS_STRIDE)       // 8448 floats
#define GEMM_SMEM_BYTES ((2 * AF_STAGE + 2 * BS_STAGE) * 4)   // 101376

template <bool RELU>
__global__ __launch_bounds__(256, 1)
void tf32gemm_kernel(const float* __restrict__ A, const float* __restrict__ B,
                     const float* __restrict__ bias, float* __restrict__ C,
                     int M, int N, int K) {
    extern __shared__ uint32_t smemraw[];
    uint32_t* Af = smemraw;                 // 2 stages fragment-major A
    uint32_t* Bs = smemraw + 2 * AF_STAGE;  // 2 stages B [k][n] stride 264

    const int tid  = threadIdx.x;
    const int warp = tid >> 5, lane = tid & 31;
    const int wm = warp >> 2;          // 0..1 -> m offset wm*64
    const int wn = warp & 3;           // 0..3 -> n offset wn*64
    const int bm = blockIdx.y * 128;
    const int bn = blockIdx.x * 256;
    const int g  = lane >> 2;          // 0..7
    const int tg = lane & 3;           // 0..3

    // A loader: 4 float4/thread; B loader: 8 float4/thread
    int arow[4], ak4[4];
#pragma unroll
    for (int i = 0; i < 4; i++) {
        int ia = tid + i * 256;
        arow[i] = ia >> 3;  ak4[i] = (ia & 7) * 4;
    }
    int brow[8], bn4[8];
#pragma unroll
    for (int i = 0; i < 8; i++) {
        int ia = tid + i * 256;
        brow[i] = ia >> 6;  bn4[i] = (ia & 63) * 4;
    }
    // A fragment-major scatter destinations
    int adst[4];
#pragma unroll
    for (int i = 0; i < 4; i++) {
        int mt = arow[i] >> 4, gg = arow[i] & 7, rb = (arow[i] >> 3) & 1;
        int ks = ak4[i] >> 3, k2 = (ak4[i] >> 2) & 1;
        adst[i] = (mt * 4 + ks) * AF_STRIDE + gg * 16 + rb + 2 * k2;
    }

    float acc[4][8][4];
#pragma unroll
    for (int mt = 0; mt < 4; mt++)
#pragma unroll
        for (int nt = 0; nt < 8; nt++)
#pragma unroll
            for (int r = 0; r < 4; r++) acc[mt][nt][r] = 0.f;

    // ---- prologue: stage chunk 0 ----
    float4 pa[4];
#pragma unroll
    for (int i = 0; i < 8; i++)
        cpasync16(smem_u32(Bs + brow[i] * BS_STRIDE + bn4[i]),
                  B + (size_t)brow[i] * N + bn + bn4[i]);
    cpasync_commit();
#pragma unroll
    for (int i = 0; i < 4; i++)
        pa[i] = *(const float4*)(A + (size_t)(bm + arow[i]) * K + ak4[i]);
#pragma unroll
    for (int i = 0; i < 4; i++) {
        uint32_t* d = Af + adst[i];
        d[0]  = f2tf32(pa[i].x);
        d[4]  = f2tf32(pa[i].y);
        d[8]  = f2tf32(pa[i].z);
        d[12] = f2tf32(pa[i].w);
    }
    cpasync_wait0();
    __syncthreads();

    int s = 0;
    for (int k0 = 0; k0 < K; k0 += 32) {
        const bool next = (k0 + 32 < K);
        if (next) {
            const int sn = s ^ 1;
#pragma unroll
            for (int i = 0; i < 8; i++)
                cpasync16(smem_u32(Bs + sn * BS_STAGE + brow[i] * BS_STRIDE + bn4[i]),
                          B + (size_t)(k0 + 32 + brow[i]) * N + bn + bn4[i]);
            cpasync_commit();
#pragma unroll
            for (int i = 0; i < 4; i++)
                pa[i] = *(const float4*)(A + (size_t)(bm + arow[i]) * K + k0 + 32 + ak4[i]);
        }

        const uint32_t* AfS = Af + s * AF_STAGE;
        const uint32_t* BsS = Bs + s * BS_STAGE;
#pragma unroll
        for (int ks = 0; ks < 4; ks++) {
            uint4 af[4];
#pragma unroll
            for (int mt = 0; mt < 4; mt++)
                af[mt] = *(const uint4*)(AfS + ((wm * 4 + mt) * 4 + ks) * AF_STRIDE + lane * 4);
            uint32_t bf[8][2];
#pragma unroll
            for (int nt = 0; nt < 8; nt++) {
                int n = wn * 64 + nt * 8 + g;
                bf[nt][0] = BsS[(ks * 8 + tg) * BS_STRIDE + n];
                bf[nt][1] = BsS[(ks * 8 + tg + 4) * BS_STRIDE + n];
            }
#pragma unroll
            for (int mt = 0; mt < 4; mt++)
#pragma unroll
                for (int nt = 0; nt < 8; nt++)
                    mma_tf32(acc[mt][nt], (const uint32_t*)&af[mt], bf[nt]);
        }

        if (next) {
            uint32_t* AfN = Af + (s ^ 1) * AF_STAGE;
#pragma unroll
            for (int i = 0; i < 4; i++) {
                uint32_t* d = AfN + adst[i];
                d[0]  = f2tf32(pa[i].x);
                d[4]  = f2tf32(pa[i].y);
                d[8]  = f2tf32(pa[i].z);
                d[12] = f2tf32(pa[i].w);
            }
        }
        cpasync_wait0();
        __syncthreads();
        s ^= 1;
    }

    // epilogue: bias + optional relu, float2 stores
#pragma unroll
    for (int nt = 0; nt < 8; nt++) {
        int n = bn + wn * 64 + nt * 8 + 2 * tg;
        float bb0 = bias[n], bb1 = bias[n + 1];
#pragma unroll
        for (int mt = 0; mt < 4; mt++) {
            int m = bm + wm * 64 + mt * 16 + g;
            float c0 = acc[mt][nt][0] + bb0;
            float c1 = acc[mt][nt][1] + bb1;
            float c2 = acc[mt][nt][2] + bb0;
            float c3 = acc[mt][nt][3] + bb1;
            if (RELU) {
                c0 = fmaxf(c0, 0.f); c1 = fmaxf(c1, 0.f);
                c2 = fmaxf(c2, 0.f); c3 = fmaxf(c3, 0.f);
            }
            *(float2*)(C + (size_t)m * N + n)       = make_float2(c0, c1);
            *(float2*)(C + (size_t)(m + 8) * N + n) = make_float2(c2, c3);
        }
    }
}

// ---------------- resnorm ---------------------------------------------------
__global__ __launch_bounds__(256)
void resnorm_kernel(const float* __restrict__ x, const float* __restrict__ fx,
                    float* __restrict__ out) {
    const size_t row = blockIdx.x;
    const size_t base = row * Dc + threadIdx.x * 4;
    float4 a = *(const float4*)(x + base);
    float4 b = *(const float4*)(fx + base);
    float4 y = make_float4(a.x + b.x, a.y + b.y, a.z + b.z, a.w + b.w);

    float s = y.x + y.y + y.z + y.w;
    float tot = blockReduceSum(s);
    float mu = tot * (1.f / (float)Dc);

    float dx = y.x - mu, dy = y.y - mu, dz = y.z - mu, dw = y.w - mu;
    float ss = dx * dx + dy * dy + dz * dz + dw * dw;
    float tss = blockReduceSum(ss);
    float sd = sqrtf(tss / (float)(Dc - 1));
    float inv = 1.f / (sd + EPSc);

    *(float4*)(out + base) = make_float4(dx * inv, dy * inv, dz * inv, dw * inv);
}

// ---------------- fused attention (unchanged from R3) ------------------------
#define TI 32
#define SP_STRIDE 1028
#define TS_STRIDE 72
#define SMEM_SP_FLOATS (TI * SP_STRIDE)
#define SMEM_KS_OFF    SMEM_SP_FLOATS
#define SMEM_QS_OFF    (SMEM_KS_OFF + TI * TS_STRIDE)
#define SMEM_TOTAL_FLOATS (SMEM_QS_OFF + 128 * TS_STRIDE)
#define ATTN_SMEM_BYTES (SMEM_TOTAL_FLOATS * 4)

__global__ __launch_bounds__(256)
void attn_fused_kernel(const float* __restrict__ Km, const float* __restrict__ Qm,
                       const float* __restrict__ Vm, float* __restrict__ O) {
    extern __shared__ float sm[];
    float*    Sp  = sm;
    uint32_t* Spu = (uint32_t*)sm;
    uint32_t* Ksu = (uint32_t*)(sm + SMEM_KS_OFF);
    uint32_t* Qsu = (uint32_t*)(sm + SMEM_QS_OFF);

    const int tid  = threadIdx.x;
    const int warp = tid >> 5, lane = tid & 31;
    const int g  = lane >> 2;
    const int tg = lane & 3;
    const int bh = blockIdx.y;
    const int b  = bh >> 4, h = bh & 15;
    const int i0 = blockIdx.x * TI;
    const size_t hb = (size_t)b * HDc + h * DQKc;

    for (int t = tid; t < TI * 16; t += 256) {
        int r = t >> 4, d4 = (t & 15) * 4;
        float4 v = *(const float4*)(Km + (size_t)(i0 + r) * HDc * Bc + hb + d4);
        uint32_t* p = Ksu + r * TS_STRIDE + d4;
        p[0] = f2tf32(v.x * 0.03125f);
        p[1] = f2tf32(v.y * 0.03125f);
        p[2] = f2tf32(v.z * 0.03125f);
        p[3] = f2tf32(v.w * 0.03125f);
    }
    __syncthreads();

    uint32_t afr[2][8][4];
#pragma unroll
    for (int mt = 0; mt < 2; mt++)
#pragma unroll
        for (int ks = 0; ks < 8; ks++) {
            int m = mt * 16 + g;
            int kk = ks * 8 + tg;
            afr[mt][ks][0] = Ksu[m * TS_STRIDE + kk];
            afr[mt][ks][1] = Ksu[(m + 8) * TS_STRIDE + kk];
            afr[mt][ks][2] = Ksu[m * TS_STRIDE + kk + 4];
            afr[mt][ks][3] = Ksu[(m + 8) * TS_STRIDE + kk + 4];
        }

    const int n0 = warp * 16;
    for (int jt = 0; jt < 8; jt++) {
        __syncthreads();
        for (int t = tid; t < 128 * 16; t += 256) {
            int r = t >> 4, d4 = (t & 15) * 4;
            int j = jt * 128 + r;
            float4 v = *(const float4*)(Qm + (size_t)j * HDc * Bc + hb + d4);
            uint32_t* p = Qsu + r * TS_STRIDE + d4;
            p[0] = f2tf32(v.x); p[1] = f2tf32(v.y);
            p[2] = f2tf32(v.z); p[3] = f2tf32(v.w);
        }
        __syncthreads();

        float acc[2][2][4];
#pragma unroll
        for (int mt = 0; mt < 2; mt++)
#pragma unroll
            for (int nt = 0; nt < 2; nt++)
#pragma unroll
                for (int r = 0; r < 4; r++) acc[mt][nt][r] = 0.f;

#pragma unroll
        for (int ks = 0; ks < 8; ks++) {
            int kk = ks * 8 + tg;
            uint32_t bf[2][2];
#pragma unroll
            for (int nt = 0; nt < 2; nt++) {
                int jl = n0 + nt * 8 + g;
                bf[nt][0] = Qsu[jl * TS_STRIDE + kk];
                bf[nt][1] = Qsu[jl * TS_STRIDE + kk + 4];
            }
#pragma unroll
            for (int mt = 0; mt < 2; mt++)
#pragma unroll
                for (int nt = 0; nt < 2; nt++)
                    mma_tf32(acc[mt][nt], afr[mt][ks], bf[nt]);
        }

#pragma unroll
        for (int mt = 0; mt < 2; mt++)
#pragma unroll
            for (int nt = 0; nt < 2; nt++) {
                int row = mt * 16 + g;
                int col = jt * 128 + n0 + nt * 8 + 2 * tg;
                Sp[row * SP_STRIDE + col]           = acc[mt][nt][0];
                Sp[row * SP_STRIDE + col + 1]       = acc[mt][nt][1];
                Sp[(row + 8) * SP_STRIDE + col]     = acc[mt][nt][2];
                Sp[(row + 8) * SP_STRIDE + col + 1] = acc[mt][nt][3];
            }
    }
    __syncthreads();

#pragma unroll
    for (int rr = 0; rr < 4; rr++) {
        int r = warp * 4 + rr;
        float4 vv[8];
#pragma unroll
        for (int k = 0; k < 8; k++)
            vv[k] = *(float4*)&Sp[r * SP_STRIDE + lane * 4 + k * 128];
        float mx = -3.4e38f;
#pragma unroll
        for (int k = 0; k < 8; k++)
            mx = fmaxf(mx, fmaxf(fmaxf(vv[k].x, vv[k].y), fmaxf(vv[k].z, vv[k].w)));
        mx = warpReduceMax(mx);
        float sum = 0.f;
#pragma unroll
        for (int k = 0; k < 8; k++) {
            vv[k].x = __expf(vv[k].x - mx); vv[k].y = __expf(vv[k].y - mx);
            vv[k].z = __expf(vv[k].z - mx); vv[k].w = __expf(vv[k].w - mx);
            sum += vv[k].x + vv[k].y + vv[k].z + vv[k].w;
        }
        sum = warpReduceSum(sum);
        float inv = 1.f / sum;
#pragma unroll
        for (int k = 0; k < 8; k++) {
            uint32_t* p = Spu + r * SP_STRIDE + lane * 4 + k * 128;
            p[0] = f2tf32(vv[k].x * inv);
            p[1] = f2tf32(vv[k].y * inv);
            p[2] = f2tf32(vv[k].z * inv);
            p[3] = f2tf32(vv[k].w * inv);
        }
    }

    const int wm = warp >> 2;
    const int wn = warp & 3;
    float oacc[2][4];
#pragma unroll
    for (int nt = 0; nt < 2; nt++)
#pragma unroll
        for (int r = 0; r < 4; r++) oacc[nt][r] = 0.f;

    for (int vt = 0; vt < 8; vt++) {
        __syncthreads();
        for (int t = tid; t < 128 * 16; t += 256) {
            int r = t >> 4, d4 = (t & 15) * 4;
            int j = vt * 128 + r;
            float4 v = *(const float4*)(Vm + (size_t)j * HDc * Bc + hb + d4);
            uint32_t* p = Qsu + r * TS_STRIDE + d4;
            p[0] = f2tf32(v.x); p[1] = f2tf32(v.y);
            p[2] = f2tf32(v.z); p[3] = f2tf32(v.w);
        }
        __syncthreads();

#pragma unroll
        for (int ks = 0; ks < 16; ks++) {
            int kk = ks * 8;
            int arow = wm * 16 + g;
            int acol = vt * 128 + kk + tg;
            uint32_t a[4];
            a[0] = Spu[arow * SP_STRIDE + acol];
            a[1] = Spu[(arow + 8) * SP_STRIDE + acol];
            a[2] = Spu[arow * SP_STRIDE + acol + 4];
            a[3] = Spu[(arow + 8) * SP_STRIDE + acol + 4];
#pragma unroll
            for (int nt = 0; nt < 2; nt++) {
                int d = wn * 16 + nt * 8 + g;
                uint32_t bf[2];
                bf[0] = Qsu[(kk + tg) * TS_STRIDE + d];
                bf[1] = Qsu[(kk + tg + 4) * TS_STRIDE + d];
                mma_tf32(oacc[nt], a, bf);
            }
        }
    }

#pragma unroll
    for (int nt = 0; nt < 2; nt++) {
        int d = wn * 16 + nt * 8 + 2 * tg;
        int m = wm * 16 + g;
        size_t a0 = (size_t)(i0 + m) * HDc * Bc + hb + d;
        size_t a1 = (size_t)(i0 + m + 8) * HDc * Bc + hb + d;
        *(float2*)(O + a0) = make_float2(oacc[nt][0], oacc[nt][1]);
        *(float2*)(O + a1) = make_float2(oacc[nt][2], oacc[nt][3]);
    }
}

// ---------------------------------------------------------------------------
extern "C" void kernel_launch(void* const* d_in, const int* in_sizes, int n_in,
                              void* d_out, int out_size) {
    (void)in_sizes; (void)n_in; (void)out_size;
    const float* x_in = (const float*)d_in[0];
    const float* Wk = (const float*)d_in[2];
    const float* bk = (const float*)d_in[3];
    const float* Wq = (const float*)d_in[4];
    const float* bq = (const float*)d_in[5];
    const float* Wv = (const float*)d_in[6];
    const float* bv = (const float*)d_in[7];
    const float* W1 = (const float*)d_in[8];
    const float* b1 = (const float*)d_in[9];
    const float* W2 = (const float*)d_in[10];
    const float* b2 = (const float*)d_in[11];
    float* out = (float*)d_out;

    float* base = nullptr;
    cudaGetSymbolAddress((void**)&base, g_scratch);
    float* g_h   = base + OFF_H;
    float* g_f   = base + OFF_F;
    float* g_z   = base + OFF_Z;
    float* g_K   = base + OFF_K;
    float* g_Q   = base + OFF_Q;
    float* g_V   = base + OFF_V;
    float* g_att = base + OFF_ATT;
    float* g_x   = base + OFF_X;
    float* g_W1r = base + OFF_W1R;
    float* g_W2r = base + OFF_W2R;
    float* g_Wkr = base + OFF_WKR;
    float* g_Wqr = base + OFF_WQR;
    float* g_Wvr = base + OFF_WVR;

    cudaFuncSetAttribute(attn_fused_kernel,
                         cudaFuncAttributeMaxDynamicSharedMemorySize,
                         ATTN_SMEM_BYTES);
    cudaFuncSetAttribute(tf32gemm_kernel<true>,
                         cudaFuncAttributeMaxDynamicSharedMemorySize,
                         GEMM_SMEM_BYTES);
    cudaFuncSetAttribute(tf32gemm_kernel<false>,
                         cudaFuncAttributeMaxDynamicSharedMemorySize,
                         GEMM_SMEM_BYTES);

    // pre-round all weights to tf32 (RNA) so the cp.async B path is exact
    round_tf32_kernel<<<(Lc * Dc * FFc) / 1024, 256>>>(W1, g_W1r);
    round_tf32_kernel<<<(Lc * FFc * Dc) / 1024, 256>>>(W2, g_W2r);
    round_tf32_kernel<<<(Lc * Dc * HDc) / 1024, 256>>>(Wk, g_Wkr);
    round_tf32_kernel<<<(Lc * Dc * HDc) / 1024, 256>>>(Wq, g_Wqr);
    round_tf32_kernel<<<(Lc * Dc * HDc) / 1024, 256>>>(Wv, g_Wvr);

    const float* cur = x_in;
    for (int l = 0; l < Lc; l++) {
        const float* W1l = g_W1r + (size_t)l * Dc * FFc;
        const float* b1l = b1 + (size_t)l * FFc;
        const float* W2l = g_W2r + (size_t)l * FFc * Dc;
        const float* b2l = b2 + (size_t)l * Dc;
        const float* Wkl = g_Wkr + (size_t)l * Dc * HDc;
        const float* bkl = bk + (size_t)l * HDc;
        const float* Wql = g_Wqr + (size_t)l * Dc * HDc;
        const float* bql = bq + (size_t)l * HDc;
        const float* Wvl = g_Wvr + (size_t)l * Dc * HDc;
        const float* bvl = bv + (size_t)l * HDc;

        tf32gemm_kernel<true><<<dim3(FFc / 256, TBc / 128), 256, GEMM_SMEM_BYTES>>>(
            cur, W1l, b1l, g_h, TBc, FFc, Dc);
        tf32gemm_kernel<true><<<dim3(Dc / 256, TBc / 128), 256, GEMM_SMEM_BYTES>>>(
            g_h, W2l, b2l, g_f, TBc, Dc, FFc);
        resnorm_kernel<<<TBc, 256>>>(cur, g_f, g_z);
        tf32gemm_kernel<false><<<dim3(HDc / 256, TBc / 128), 256, GEMM_SMEM_BYTES>>>(
            g_z, Wkl, bkl, g_K, TBc, HDc, Dc);
        tf32gemm_kernel<false><<<dim3(HDc / 256, TBc / 128), 256, GEMM_SMEM_BYTES>>>(
            g_z, Wql, bql, g_Q, TBc, HDc, Dc);
        tf32gemm_kernel<false><<<dim3(HDc / 256, TBc / 128), 256, GEMM_SMEM_BYTES>>>(
            g_z, Wvl, bvl, g_V, TBc, HDc, Dc);

        attn_fused_kernel<<<dim3(Tc / TI, Bc * Hc), 256, ATTN_SMEM_BYTES>>>(
            g_K, g_Q, g_V, g_att);

        resnorm_kernel<<<TBc, 256>>>(g_z, g_att, (l == Lc - 1) ? out : g_x);
        cur = g_x;
    }
}

// round 17
// speedup vs baseline: 1.3714x; 1.3714x over previous
#include <cuda_runtime.h>
#include <cuda_fp16.h>
#include <math.h>
#include <stdint.h>

// ---------------------------------------------------------------------------
// TinyTransformer: L=4, T=1024, B=4, D=1024, H=16, DQK=DV=64, FF=4096
// Round 17 (= R10 resubmit; infra timeouts R10-R16): fp16 HMMA GEMMs
// (mma.sync.m16n8k16 + ldmatrix + cp.async double buffering; operands
// pre-converted to fp16). tcgen05 unavailable (ptxas target sm_103).
// Attention (tf32) + resnorm kept.
// ---------------------------------------------------------------------------

#define Lc   4
#define Tc   1024
#define Bc   4
#define Dc   1024
#define Hc   16
#define DQKc 64
#define DVc  64
#define FFc  4096
#define TBc  4096
#define HDc  1024
#define EPSc 1e-6f

// ---------------- scratch (static device memory; floats) --------------------
#define OFF_HH   0                          // h fp16: TB*FF/2 = 8388608
#define OFF_F    8388608                    // f fp32: 4194304
#define OFF_Z    (OFF_F   + 4194304)
#define OFF_ZH   (OFF_Z   + 4194304)        // z fp16: 2097152
#define OFF_K    (OFF_ZH  + 2097152)
#define OFF_Q    (OFF_K   + 4194304)
#define OFF_V    (OFF_Q   + 4194304)
#define OFF_ATT  (OFF_V   + 4194304)
#define OFF_X    (OFF_ATT + 4194304)
#define OFF_XH   (OFF_X   + 4194304)        // x fp16: 2097152
#define OFF_W1T  (OFF_XH  + 2097152)        // fp16 [FF,D] xL: 8388608
#define OFF_W2T  (OFF_W1T + 8388608)        // fp16 [D,FF] xL: 8388608
#define OFF_WKT  (OFF_W2T + 8388608)        // fp16 [HD,D] xL: 2097152
#define OFF_WQT  (OFF_WKT + 2097152)
#define OFF_WVT  (OFF_WQT + 2097152)
#define SCRATCH_FLOATS (OFF_WVT + 2097152)

__device__ float g_scratch[SCRATCH_FLOATS];

// ---------------- reductions ------------------------------------------------
__device__ __forceinline__ float warpReduceSum(float v) {
#pragma unroll
    for (int o = 16; o > 0; o >>= 1) v += __shfl_xor_sync(0xffffffffu, v, o);
    return v;
}
__device__ __forceinline__ float warpReduceMax(float v) {
#pragma unroll
    for (int o = 16; o > 0; o >>= 1) v = fmaxf(v, __shfl_xor_sync(0xffffffffu, v, o));
    return v;
}
__device__ float blockReduceSum(float v) {
    __shared__ float s[8];
    int lane = threadIdx.x & 31, w = threadIdx.x >> 5;
    v = warpReduceSum(v);
    if (lane == 0) s[w] = v;
    __syncthreads();
    float r = 0.f;
    if (threadIdx.x < 8) r = s[threadIdx.x];
    if (w == 0) r = warpReduceSum(r);
    if (threadIdx.x == 0) s[0] = r;
    __syncthreads();
    r = s[0];
    __syncthreads();
    return r;
}

// ---------------- helpers ---------------------------------------------------
__device__ __forceinline__ uint32_t f2tf32(float x) {
    uint32_t r;
    asm("cvt.rna.tf32.f32 %0, %1;" : "=r"(r) : "f"(x));
    return r;
}
__device__ __forceinline__ void mma_tf32(float c[4], const uint32_t a[4],
                                         const uint32_t b[2]) {
    asm volatile(
        "mma.sync.aligned.m16n8k8.row.col.f32.tf32.tf32.f32 "
        "{%0,%1,%2,%3}, {%4,%5,%6,%7}, {%8,%9}, {%0,%1,%2,%3};"
        : "+f"(c[0]), "+f"(c[1]), "+f"(c[2]), "+f"(c[3])
        : "r"(a[0]), "r"(a[1]), "r"(a[2]), "r"(a[3]), "r"(b[0]), "r"(b[1]));
}
__device__ __forceinline__ void mma_f16(float c[4], const uint32_t a[4],
                                        const uint32_t b[2]) {
    asm volatile(
        "mma.sync.aligned.m16n8k16.row.col.f32.f16.f16.f32 "
        "{%0,%1,%2,%3}, {%4,%5,%6,%7}, {%8,%9}, {%0,%1,%2,%3};"
        : "+f"(c[0]), "+f"(c[1]), "+f"(c[2]), "+f"(c[3])
        : "r"(a[0]), "r"(a[1]), "r"(a[2]), "r"(a[3]), "r"(b[0]), "r"(b[1]));
}
#define LDSM_X4(r, addr) \
    asm volatile("ldmatrix.sync.aligned.m8n8.x4.shared.b16 {%0,%1,%2,%3}, [%4];" \
        : "=r"((r)[0]), "=r"((r)[1]), "=r"((r)[2]), "=r"((r)[3]) : "r"(addr))

__device__ __forceinline__ uint32_t smem_u32(const void* p) {
    return (uint32_t)__cvta_generic_to_shared(p);
}
__device__ __forceinline__ void cpasync16(uint32_t dst, const void* src) {
    asm volatile("cp.async.ca.shared.global [%0], [%1], 16;" :: "r"(dst), "l"(src));
}
__device__ __forceinline__ void cpasync_commit() {
    asm volatile("cp.async.commit_group;");
}
__device__ __forceinline__ void cpasync_wait0() {
    asm volatile("cp.async.wait_group 0;");
}

// ---------------- prep kernels ----------------------------------------------
__global__ __launch_bounds__(256)
void f32_to_f16_kernel(const float* __restrict__ in, __half* __restrict__ outp) {
    int i = blockIdx.x * 256 + threadIdx.x;
    float4 v = ((const float4*)in)[i];
    __half2* o = (__half2*)outp;
    o[i * 2]     = __floats2half2_rn(v.x, v.y);
    o[i * 2 + 1] = __floats2half2_rn(v.z, v.w);
}

// out[c][r] = fp16(in[r][c]); batched over blockIdx.z (stride R*C elements)
__global__ __launch_bounds__(256)
void transpose_f16_kernel(const float* __restrict__ in, __half* __restrict__ outp,
                          int R, int C) {
    __shared__ float t[32][33];
    const size_t off = (size_t)blockIdx.z * R * C;
    in += off; outp += off;
    const int c0 = blockIdx.x * 32, r0 = blockIdx.y * 32;
    const int tx = threadIdx.x & 31, ty = threadIdx.x >> 5;
#pragma unroll
    for (int i = 0; i < 4; i++)
        t[ty + i * 8][tx] = in[(size_t)(r0 + ty + i * 8) * C + c0 + tx];
    __syncthreads();
#pragma unroll
    for (int i = 0; i < 4; i++)
        outp[(size_t)(c0 + ty + i * 8) * R + r0 + tx] =
            __float2half_rn(t[tx][ty + i * 8]);
}

// ---------------- fp16 GEMM --------------------------------------------------
// C[M,N] = relu?(A[M,K] @ Bt[N,K]^T + bias). A, Bt fp16; C fp32 or fp16.
// Block 128x128, k-chunk 32. 256 threads = 8 warps (2x4), warp tile 64x32.
// smem: per stage A[128][40] fp16 (10240B) + B[128][40] fp16; 2 stages = 40KB.
// stride 40 halfs = 80B -> ldmatrix rows cover all 32 banks (conflict-free).
#define HROW_B   80
#define HTILE_B  (128 * HROW_B)       // 10240
#define HSTAGE_B (2 * HTILE_B)        // 20480

template <bool RELU, bool OUT16>
__global__ __launch_bounds__(256)
void h16gemm_kernel(const __half* __restrict__ A, const __half* __restrict__ Bt,
                    const float* __restrict__ bias, float* __restrict__ C,
                    __half* __restrict__ Ch, int M, int N, int K) {
    __shared__ __align__(16) char hsm[2 * HSTAGE_B];
    const uint32_t sb = smem_u32(hsm);

    const int tid  = threadIdx.x;
    const int warp = tid >> 5, lane = tid & 31;
    const int wm = warp >> 2;          // 0..1 -> m offset 64
    const int wn = warp & 3;           // 0..3 -> n offset 32
    const int m0 = blockIdx.y * 128;
    const int n0 = blockIdx.x * 128;
    const int g  = lane >> 2;
    const int tg = lane & 3;

    // loaders: A tile 512 x 16B units, B tile 512; 2 each per thread
    int lrow[2], lsgh[2], lsgb[2];
#pragma unroll
    for (int i = 0; i < 2; i++) {
        int u = tid + i * 256;
        lrow[i] = u >> 2;
        lsgh[i] = (u & 3) * 8;     // half-element offset
        lsgb[i] = (u & 3) * 16;    // byte offset
    }

    // ldmatrix per-lane addresses (within-tile byte offsets, ks=0)
    const int j = lane >> 3, rr = lane & 7;
    const int jrow = (j & 1) * 8 + rr;
    const int kofb = (j >> 1) * 16;
    uint32_t aoff[4], boff[2];
#pragma unroll
    for (int mt = 0; mt < 4; mt++)
        aoff[mt] = (uint32_t)((wm * 64 + mt * 16 + jrow) * HROW_B + kofb);
#pragma unroll
    for (int np = 0; np < 2; np++)
        boff[np] = (uint32_t)((wn * 32 + np * 16 + jrow) * HROW_B + kofb);

    float acc[4][4][4];
#pragma unroll
    for (int mt = 0; mt < 4; mt++)
#pragma unroll
        for (int nt = 0; nt < 4; nt++)
#pragma unroll
            for (int r = 0; r < 4; r++) acc[mt][nt][r] = 0.f;

    // prologue: stage chunk 0 into stage 0
#pragma unroll
    for (int i = 0; i < 2; i++) {
        cpasync16(sb + lrow[i] * HROW_B + lsgb[i],
                  A + (size_t)(m0 + lrow[i]) * K + lsgh[i]);
        cpasync16(sb + HTILE_B + lrow[i] * HROW_B + lsgb[i],
                  Bt + (size_t)(n0 + lrow[i]) * K + lsgh[i]);
    }
    cpasync_commit();
    cpasync_wait0();
    __syncthreads();

    int s = 0;
    for (int k0 = 0; k0 < K; k0 += 32) {
        const bool next = (k0 + 32 < K);
        if (next) {
            const uint32_t nb = sb + (s ^ 1) * HSTAGE_B;
#pragma unroll
            for (int i = 0; i < 2; i++) {
                cpasync16(nb + lrow[i] * HROW_B + lsgb[i],
                          A + (size_t)(m0 + lrow[i]) * K + k0 + 32 + lsgh[i]);
                cpasync16(nb + HTILE_B + lrow[i] * HROW_B + lsgb[i],
                          Bt + (size_t)(n0 + lrow[i]) * K + k0 + 32 + lsgh[i]);
            }
            cpasync_commit();
        }

        const uint32_t Ab = sb + s * HSTAGE_B;
        const uint32_t Bb = Ab + HTILE_B;
#pragma unroll
        for (int ks = 0; ks < 2; ks++) {
            uint32_t a[4][4];
#pragma unroll
            for (int mt = 0; mt < 4; mt++)
                LDSM_X4(a[mt], Ab + aoff[mt] + ks * 32);
            uint32_t bregs[2][4];
#pragma unroll
            for (int np = 0; np < 2; np++)
                LDSM_X4(bregs[np], Bb + boff[np] + ks * 32);
#pragma unroll
            for (int mt = 0; mt < 4; mt++)
#pragma unroll
                for (int nt = 0; nt < 4; nt++) {
                    const int np = nt >> 1, odd = nt & 1;
                    uint32_t b2[2] = {bregs[np][odd], bregs[np][2 + odd]};
                    mma_f16(acc[mt][nt], a[mt], b2);
                }
        }

        if (next) cpasync_wait0();
        __syncthreads();
        s ^= 1;
    }

    // epilogue
#pragma unroll
    for (int nt = 0; nt < 4; nt++) {
        const int n = n0 + wn * 32 + nt * 8 + 2 * tg;
        const float bb0 = bias[n], bb1 = bias[n + 1];
#pragma unroll
        for (int mt = 0; mt < 4; mt++) {
            const int m = m0 + wm * 64 + mt * 16 + g;
            float c0 = acc[mt][nt][0] + bb0;
            float c1 = acc[mt][nt][1] + bb1;
            float c2 = acc[mt][nt][2] + bb0;
            float c3 = acc[mt][nt][3] + bb1;
            if (RELU) {
                c0 = fmaxf(c0, 0.f); c1 = fmaxf(c1, 0.f);
                c2 = fmaxf(c2, 0.f); c3 = fmaxf(c3, 0.f);
            }
            if (OUT16) {
                *(__half2*)(Ch + (size_t)m * N + n)       = __floats2half2_rn(c0, c1);
                *(__half2*)(Ch + (size_t)(m + 8) * N + n) = __floats2half2_rn(c2, c3);
            } else {
                *(float2*)(C + (size_t)m * N + n)       = make_float2(c0, c1);
                *(float2*)(C + (size_t)(m + 8) * N + n) = make_float2(c2, c3);
            }
        }
    }
}

// ---------------- resnorm (fp32 out + fp16 copy) -----------------------------
__global__ __launch_bounds__(256)
void resnorm_kernel(const float* __restrict__ x, const float* __restrict__ fx,
                    float* __restrict__ out, __half* __restrict__ outh) {
    const size_t row = blockIdx.x;
    const size_t base = row * Dc + threadIdx.x * 4;
    float4 a = *(const float4*)(x + base);
    float4 b = *(const float4*)(fx + base);
    float4 y = make_float4(a.x + b.x, a.y + b.y, a.z + b.z, a.w + b.w);

    float s = y.x + y.y + y.z + y.w;
    float tot = blockReduceSum(s);
    float mu = tot * (1.f / (float)Dc);

    float dx = y.x - mu, dy = y.y - mu, dz = y.z - mu, dw = y.w - mu;
    float ss = dx * dx + dy * dy + dz * dz + dw * dw;
    float tss = blockReduceSum(ss);
    float sd = sqrtf(tss / (float)(Dc - 1));
    float inv = 1.f / (sd + EPSc);

    float4 o = make_float4(dx * inv, dy * inv, dz * inv, dw * inv);
    *(float4*)(out + base) = o;
    __half2* oh = (__half2*)(outh + base);
    oh[0] = __floats2half2_rn(o.x, o.y);
    oh[1] = __floats2half2_rn(o.z, o.w);
}

// ---------------- fused attention (tf32, unchanged from R3) ------------------
#define TI 32
#define SP_STRIDE 1028
#define TS_STRIDE 72
#define SMEM_SP_FLOATS (TI * SP_STRIDE)
#define SMEM_KS_OFF    SMEM_SP_FLOATS
#define SMEM_QS_OFF    (SMEM_KS_OFF + TI * TS_STRIDE)
#define SMEM_TOTAL_FLOATS (SMEM_QS_OFF + 128 * TS_STRIDE)
#define ATTN_SMEM_BYTES (SMEM_TOTAL_FLOATS * 4)

__global__ __launch_bounds__(256)
void attn_fused_kernel(const float* __restrict__ Km, const float* __restrict__ Qm,
                       const float* __restrict__ Vm, float* __restrict__ O) {
    extern __shared__ float sm[];
    float*    Sp  = sm;
    uint32_t* Spu = (uint32_t*)sm;
    uint32_t* Ksu = (uint32_t*)(sm + SMEM_KS_OFF);
    uint32_t* Qsu = (uint32_t*)(sm + SMEM_QS_OFF);

    const int tid  = threadIdx.x;
    const int warp = tid >> 5, lane = tid & 31;
    const int g  = lane >> 2;
    const int tg = lane & 3;
    const int bh = blockIdx.y;
    const int b  = bh >> 4, h = bh & 15;
    const int i0 = blockIdx.x * TI;
    const size_t hb = (size_t)b * HDc + h * DQKc;

    for (int t = tid; t < TI * 16; t += 256) {
        int r = t >> 4, d4 = (t & 15) * 4;
        float4 v = *(const float4*)(Km + (size_t)(i0 + r) * HDc * Bc + hb + d4);
        uint32_t* p = Ksu + r * TS_STRIDE + d4;
        p[0] = f2tf32(v.x * 0.03125f);
        p[1] = f2tf32(v.y * 0.03125f);
        p[2] = f2tf32(v.z * 0.03125f);
        p[3] = f2tf32(v.w * 0.03125f);
    }
    __syncthreads();

    uint32_t afr[2][8][4];
#pragma unroll
    for (int mt = 0; mt < 2; mt++)
#pragma unroll
        for (int ks = 0; ks < 8; ks++) {
            int m = mt * 16 + g;
            int kk = ks * 8 + tg;
            afr[mt][ks][0] = Ksu[m * TS_STRIDE + kk];
            afr[mt][ks][1] = Ksu[(m + 8) * TS_STRIDE + kk];
            afr[mt][ks][2] = Ksu[m * TS_STRIDE + kk + 4];
            afr[mt][ks][3] = Ksu[(m + 8) * TS_STRIDE + kk + 4];
        }

    const int n0 = warp * 16;
    for (int jt = 0; jt < 8; jt++) {
        __syncthreads();
        for (int t = tid; t < 128 * 16; t += 256) {
            int r = t >> 4, d4 = (t & 15) * 4;
            int jj = jt * 128 + r;
            float4 v = *(const float4*)(Qm + (size_t)jj * HDc * Bc + hb + d4);
            uint32_t* p = Qsu + r * TS_STRIDE + d4;
            p[0] = f2tf32(v.x); p[1] = f2tf32(v.y);
            p[2] = f2tf32(v.z); p[3] = f2tf32(v.w);
        }
        __syncthreads();

        float acc[2][2][4];
#pragma unroll
        for (int mt = 0; mt < 2; mt++)
#pragma unroll
            for (int nt = 0; nt < 2; nt++)
#pragma unroll
                for (int r = 0; r < 4; r++) acc[mt][nt][r] = 0.f;

#pragma unroll
        for (int ks = 0; ks < 8; ks++) {
            int kk = ks * 8 + tg;
            uint32_t bf[2][2];
#pragma unroll
            for (int nt = 0; nt < 2; nt++) {
                int jl = n0 + nt * 8 + g;
                bf[nt][0] = Qsu[jl * TS_STRIDE + kk];
                bf[nt][1] = Qsu[jl * TS_STRIDE + kk + 4];
            }
#pragma unroll
            for (int mt = 0; mt < 2; mt++)
#pragma unroll
                for (int nt = 0; nt < 2; nt++)
                    mma_tf32(acc[mt][nt], afr[mt][ks], bf[nt]);
        }

#pragma unroll
        for (int mt = 0; mt < 2; mt++)
#pragma unroll
            for (int nt = 0; nt < 2; nt++) {
                int row = mt * 16 + g;
                int col = jt * 128 + n0 + nt * 8 + 2 * tg;
                Sp[row * SP_STRIDE + col]           = acc[mt][nt][0];
                Sp[row * SP_STRIDE + col + 1]       = acc[mt][nt][1];
                Sp[(row + 8) * SP_STRIDE + col]     = acc[mt][nt][2];
                Sp[(row + 8) * SP_STRIDE + col + 1] = acc[mt][nt][3];
            }
    }
    __syncthreads();

#pragma unroll
    for (int rr = 0; rr < 4; rr++) {
        int r = warp * 4 + rr;
        float4 vv[8];
#pragma unroll
        for (int k = 0; k < 8; k++)
            vv[k] = *(float4*)&Sp[r * SP_STRIDE + lane * 4 + k * 128];
        float mx = -3.4e38f;
#pragma unroll
        for (int k = 0; k < 8; k++)
            mx = fmaxf(mx, fmaxf(fmaxf(vv[k].x, vv[k].y), fmaxf(vv[k].z, vv[k].w)));
        mx = warpReduceMax(mx);
        float sum = 0.f;
#pragma unroll
        for (int k = 0; k < 8; k++) {
            vv[k].x = __expf(vv[k].x - mx); vv[k].y = __expf(vv[k].y - mx);
            vv[k].z = __expf(vv[k].z - mx); vv[k].w = __expf(vv[k].w - mx);
            sum += vv[k].x + vv[k].y + vv[k].z + vv[k].w;
        }
        sum = warpReduceSum(sum);
        float inv = 1.f / sum;
#pragma unroll
        for (int k = 0; k < 8; k++) {
            uint32_t* p = Spu + r * SP_STRIDE + lane * 4 + k * 128;
            p[0] = f2tf32(vv[k].x * inv);
            p[1] = f2tf32(vv[k].y * inv);
            p[2] = f2tf32(vv[k].z * inv);
            p[3] = f2tf32(vv[k].w * inv);
        }
    }

    const int wm = warp >> 2;
    const int wn = warp & 3;
    float oacc[2][4];
#pragma unroll
    for (int nt = 0; nt < 2; nt++)
#pragma unroll
        for (int r = 0; r < 4; r++) oacc[nt][r] = 0.f;

    for (int vt = 0; vt < 8; vt++) {
        __syncthreads();
        for (int t = tid; t < 128 * 16; t += 256) {
            int r = t >> 4, d4 = (t & 15) * 4;
            int jj = vt * 128 + r;
            float4 v = *(const float4*)(Vm + (size_t)jj * HDc * Bc + hb + d4);
            uint32_t* p = Qsu + r * TS_STRIDE + d4;
            p[0] = f2tf32(v.x); p[1] = f2tf32(v.y);
            p[2] = f2tf32(v.z); p[3] = f2tf32(v.w);
        }
        __syncthreads();

#pragma unroll
        for (int ks = 0; ks < 16; ks++) {
            int kk = ks * 8;
            int arow = wm * 16 + g;
            int acol = vt * 128 + kk + tg;
            uint32_t a[4];
            a[0] = Spu[arow * SP_STRIDE + acol];
            a[1] = Spu[(arow + 8) * SP_STRIDE + acol];
            a[2] = Spu[arow * SP_STRIDE + acol + 4];
            a[3] = Spu[(arow + 8) * SP_STRIDE + acol + 4];
#pragma unroll
            for (int nt = 0; nt < 2; nt++) {
                int d = wn * 16 + nt * 8 + g;
                uint32_t bf[2];
                bf[0] = Qsu[(kk + tg) * TS_STRIDE + d];
                bf[1] = Qsu[(kk + tg + 4) * TS_STRIDE + d];
                mma_tf32(oacc[nt], a, bf);
            }
        }
    }

#pragma unroll
    for (int nt = 0; nt < 2; nt++) {
        int d = wn * 16 + nt * 8 + 2 * tg;
        int m = wm * 16 + g;
        size_t a0 = (size_t)(i0 + m) * HDc * Bc + hb + d;
        size_t a1 = (size_t)(i0 + m + 8) * HDc * Bc + hb + d;
        *(float2*)(O + a0) = make_float2(oacc[nt][0], oacc[nt][1]);
        *(float2*)(O + a1) = make_float2(oacc[nt][2], oacc[nt][3]);
    }
}

// ---------------------------------------------------------------------------
extern "C" void kernel_launch(void* const* d_in, const int* in_sizes, int n_in,
                              void* d_out, int out_size) {
    (void)in_sizes; (void)n_in; (void)out_size;
    const float* x_in = (const float*)d_in[0];
    const float* Wk = (const float*)d_in[2];
    const float* bk = (const float*)d_in[3];
    const float* Wq = (const float*)d_in[4];
    const float* bq = (const float*)d_in[5];
    const float* Wv = (const float*)d_in[6];
    const float* bv = (const float*)d_in[7];
    const float* W1 = (const float*)d_in[8];
    const float* b1 = (const float*)d_in[9];
    const float* W2 = (const float*)d_in[10];
    const float* b2 = (const float*)d_in[11];
    float* out = (float*)d_out;

    float* base = nullptr;
    cudaGetSymbolAddress((void**)&base, g_scratch);
    __half* g_hh  = (__half*)(base + OFF_HH);
    float*  g_f   = base + OFF_F;
    float*  g_z   = base + OFF_Z;
    __half* g_zh  = (__half*)(base + OFF_ZH);
    float*  g_K   = base + OFF_K;
    float*  g_Q   = base + OFF_Q;
    float*  g_V   = base + OFF_V;
    float*  g_att = base + OFF_ATT;
    float*  g_x   = base + OFF_X;
    __half* g_xh  = (__half*)(base + OFF_XH);
    __half* g_W1t = (__half*)(base + OFF_W1T);
    __half* g_W2t = (__half*)(base + OFF_W2T);
    __half* g_Wkt = (__half*)(base + OFF_WKT);
    __half* g_Wqt = (__half*)(base + OFF_WQT);
    __half* g_Wvt = (__half*)(base + OFF_WVT);

    cudaFuncSetAttribute(attn_fused_kernel,
                         cudaFuncAttributeMaxDynamicSharedMemorySize,
                         ATTN_SMEM_BYTES);

    // weight prep: transpose [K,N] -> [N,K] fp16; x -> fp16
    transpose_f16_kernel<<<dim3(FFc / 32, Dc / 32, Lc), 256>>>(W1, g_W1t, Dc, FFc);
    transpose_f16_kernel<<<dim3(Dc / 32, FFc / 32, Lc), 256>>>(W2, g_W2t, FFc, Dc);
    transpose_f16_kernel<<<dim3(HDc / 32, Dc / 32, Lc), 256>>>(Wk, g_Wkt, Dc, HDc);
    transpose_f16_kernel<<<dim3(HDc / 32, Dc / 32, Lc), 256>>>(Wq, g_Wqt, Dc, HDc);
    transpose_f16_kernel<<<dim3(HDc / 32, Dc / 32, Lc), 256>>>(Wv, g_Wvt, Dc, HDc);
    f32_to_f16_kernel<<<(TBc * Dc) / 1024, 256>>>(x_in, g_xh);

    const float*  cur_f = x_in;   // fp32 residual path
    const __half* cur_h = g_xh;   // fp16 GEMM A path
    for (int l = 0; l < Lc; l++) {
        const __half* W1l = g_W1t + (size_t)l * Dc * FFc;
        const float*  b1l = b1 + (size_t)l * FFc;
        const __half* W2l = g_W2t + (size_t)l * FFc * Dc;
        const float*  b2l = b2 + (size_t)l * Dc;
        const __half* Wkl = g_Wkt + (size_t)l * Dc * HDc;
        const float*  bkl = bk + (size_t)l * HDc;
        const __half* Wql = g_Wqt + (size_t)l * Dc * HDc;
        const float*  bql = bq + (size_t)l * HDc;
        const __half* Wvl = g_Wvt + (size_t)l * Dc * HDc;
        const float*  bvl = bv + (size_t)l * HDc;

        // FF: h = relu(x@W1+b1) -> fp16 only; f = relu(h@W2+b2) -> fp32
        h16gemm_kernel<true, true><<<dim3(FFc / 128, TBc / 128), 256>>>(
            cur_h, W1l, b1l, nullptr, g_hh, TBc, FFc, Dc);
        h16gemm_kernel<true, false><<<dim3(Dc / 128, TBc / 128), 256>>>(
            g_hh, W2l, b2l, g_f, nullptr, TBc, Dc, FFc);
        resnorm_kernel<<<TBc, 256>>>(cur_f, g_f, g_z, g_zh);
        // QKV (fp32 outputs for attention)
        h16gemm_kernel<false, false><<<dim3(HDc / 128, TBc / 128), 256>>>(
            g_zh, Wkl, bkl, g_K, nullptr, TBc, HDc, Dc);
        h16gemm_kernel<false, false><<<dim3(HDc / 128, TBc / 128), 256>>>(
            g_zh, Wql, bql, g_Q, nullptr, TBc, HDc, Dc);
        h16gemm_kernel<false, false><<<dim3(HDc / 128, TBc / 128), 256>>>(
            g_zh, Wvl, bvl, g_V, nullptr, TBc, HDc, Dc);

        attn_fused_kernel<<<dim3(Tc / TI, Bc * Hc), 256, ATTN_SMEM_BYTES>>>(
            g_K, g_Q, g_V, g_att);

        resnorm_kernel<<<TBc, 256>>>(g_z, g_att, (l == Lc - 1) ? out : g_x, g_xh);
        cur_f = g_x;
        cur_h = g_xh;
    }
}